// round 8
// baseline (speedup 1.0000x reference)
#include <cuda_runtime.h>
#include <cuda_bf16.h>
#include <cstdint>

#define B_   128
#define S_   1024
#define I_   128
#define H_   256
#define OFF_SLOPE 0.001f

// ---------------- device scratch (static, no allocations) ----------------
__device__ __align__(16) float g_G[134217728];          // [B*S][1024] = 512 MB
__device__ __align__(16) unsigned g_hpack[2][B_ * H_];  // packed (bf16 hi | lo<<16)
__device__ unsigned g_cnt[16];                          // per-group barrier counters

__device__ __forceinline__ void split_pack(float x, float y,
                                           uint32_t& hi, uint32_t& lo) {
    __nv_bfloat16 hx = __float2bfloat16(x);
    __nv_bfloat16 hy = __float2bfloat16(y);
    __nv_bfloat16 lx = __float2bfloat16(x - __bfloat162float(hx));
    __nv_bfloat16 ly = __float2bfloat16(y - __bfloat162float(hy));
    hi = (uint32_t)__bfloat16_as_ushort(hx) | ((uint32_t)__bfloat16_as_ushort(hy) << 16);
    lo = (uint32_t)__bfloat16_as_ushort(lx) | ((uint32_t)__bfloat16_as_ushort(ly) << 16);
}

__device__ __forceinline__ void mma_bf16(float4& d, const uint32_t* a,
                                         uint32_t b0, uint32_t b1) {
    asm volatile(
        "mma.sync.aligned.m16n8k16.row.col.f32.bf16.bf16.f32 "
        "{%0,%1,%2,%3}, {%4,%5,%6,%7}, {%8,%9}, {%0,%1,%2,%3};"
        : "+f"(d.x), "+f"(d.y), "+f"(d.z), "+f"(d.w)
        : "r"(a[0]), "r"(a[1]), "r"(a[2]), "r"(a[3]), "r"(b0), "r"(b1));
}

// ---------------- init ----------------
__global__ void init_k() {
    unsigned t = blockIdx.x * blockDim.x + threadIdx.x;
    if (t < 16) g_cnt[t] = 0u;
    for (unsigned i = t; i < 2u * B_ * H_; i += gridDim.x * blockDim.x)
        ((unsigned*)g_hpack)[i] = 0u;
}

// ---------------- phase A: G = x @ W + bias (bf16x3 tensor-core GEMM) ----
__global__ __launch_bounds__(256) void gemm_xw_mma(const float* __restrict__ X,
                                                   const float* __restrict__ Wm,
                                                   const float* __restrict__ bias) {
    extern __shared__ uint32_t sm[];
    uint32_t* Axh = sm;
    uint32_t* Axl = Axh + 128 * 66;
    uint32_t* Bnh = Axl + 128 * 66;
    uint32_t* Bnl = Bnh + 128 * 66;

    const int m0 = blockIdx.x * 128;
    const int n0 = blockIdx.y * 128;
    const int tid = threadIdx.x;
    const int lane = tid & 31, w = tid >> 5;
    const int gp = lane >> 2, t4 = lane & 3;
    const int wm = w >> 1, wn = w & 1;

#pragma unroll
    for (int j = 0; j < 16; j++) {
        int lin = tid + j * 256;
        int m = lin >> 5, c = lin & 31;
        float4 v = reinterpret_cast<const float4*>(X)[(size_t)(m0 + m) * 32 + c];
        uint32_t h0, l0, h1, l1;
        split_pack(v.x, v.y, h0, l0);
        split_pack(v.z, v.w, h1, l1);
        Axh[m * 66 + 2 * c] = h0; Axh[m * 66 + 2 * c + 1] = h1;
        Axl[m * 66 + 2 * c] = l0; Axl[m * 66 + 2 * c + 1] = l1;
    }
    {
        const int n = tid & 127, kh = tid >> 7;
        const float* wp = Wm + (size_t)(kh * 64) * 1024 + n0 + n;
        uint32_t* dh = &Bnh[n * 66 + kh * 32];
        uint32_t* dl = &Bnl[n * 66 + kh * 32];
#pragma unroll
        for (int j = 0; j < 32; j++) {
            float a = wp[(size_t)(2 * j) * 1024];
            float b = wp[(size_t)(2 * j + 1) * 1024];
            uint32_t h, l; split_pack(a, b, h, l);
            dh[j] = h; dl[j] = l;
        }
    }
    __syncthreads();

    float4 acc[2][8];
#pragma unroll
    for (int mt = 0; mt < 2; mt++)
#pragma unroll
        for (int nt = 0; nt < 8; nt++) acc[mt][nt] = make_float4(0.f, 0.f, 0.f, 0.f);

#pragma unroll
    for (int ks = 0; ks < 8; ks++) {
        uint32_t ah[2][4], al[2][4];
#pragma unroll
        for (int mt = 0; mt < 2; mt++) {
            const int r0 = (wm * 32 + mt * 16 + gp) * 66 + ks * 8;
            ah[mt][0] = Axh[r0 + t4];       ah[mt][1] = Axh[r0 + 8 * 66 + t4];
            ah[mt][2] = Axh[r0 + t4 + 4];   ah[mt][3] = Axh[r0 + 8 * 66 + t4 + 4];
            al[mt][0] = Axl[r0 + t4];       al[mt][1] = Axl[r0 + 8 * 66 + t4];
            al[mt][2] = Axl[r0 + t4 + 4];   al[mt][3] = Axl[r0 + 8 * 66 + t4 + 4];
        }
#pragma unroll
        for (int nt = 0; nt < 8; nt++) {
            const int c0 = (wn * 64 + nt * 8 + gp) * 66 + ks * 8;
            uint32_t bh0 = Bnh[c0 + t4], bh1 = Bnh[c0 + t4 + 4];
            uint32_t bl0 = Bnl[c0 + t4], bl1 = Bnl[c0 + t4 + 4];
#pragma unroll
            for (int mt = 0; mt < 2; mt++) {
                mma_bf16(acc[mt][nt], ah[mt], bh0, bh1);
                mma_bf16(acc[mt][nt], ah[mt], bl0, bl1);
                mma_bf16(acc[mt][nt], al[mt], bh0, bh1);
            }
        }
    }

#pragma unroll
    for (int nt = 0; nt < 8; nt++) {
        const int n = n0 + wn * 64 + nt * 8 + 2 * t4;
        float2 bv = *reinterpret_cast<const float2*>(bias + n);
#pragma unroll
        for (int mt = 0; mt < 2; mt++) {
            const int m = m0 + wm * 32 + mt * 16 + gp;
            float4 d = acc[mt][nt];
            *reinterpret_cast<float2*>(&g_G[(size_t)m * 1024 + n]) =
                make_float2(d.x + bv.x, d.y + bv.y);
            *reinterpret_cast<float2*>(&g_G[(size_t)(m + 8) * 1024 + n]) =
                make_float2(d.z + bv.x, d.w + bv.y);
        }
    }
}

// ---------------- phase B: persistent recurrent kernel (HMMA, 2-slot) ----
__device__ __forceinline__ float sigf(float x) { return 1.0f / (1.0f + __expf(-x)); }

__device__ __forceinline__ unsigned ld_acq(const unsigned* p) {
    unsigned v;
    asm volatile("ld.global.acquire.gpu.u32 %0, [%1];" : "=r"(v) : "l"(p) : "memory");
    return v;
}
__device__ __forceinline__ void red_release(unsigned* p) {
    unsigned one = 1u;
    asm volatile("red.release.gpu.global.add.u32 [%0], %1;" :: "l"(p), "r"(one) : "memory");
}
__device__ __forceinline__ void poll_ge(const unsigned* p, unsigned tgt) {
    while (ld_acq(p) < tgt) { __nanosleep(32); }
}
__device__ __forceinline__ uint4 ldcg_u4(const uint4* p) {
    uint4 v;
    asm volatile("ld.global.cg.v4.u32 {%0,%1,%2,%3}, [%4];"
                 : "=r"(v.x), "=r"(v.y), "=r"(v.z), "=r"(v.w) : "l"(p));
    return v;
}

// one interleave-slot step: stage -> MMA(bf16x3) -> cell -> publish.
__device__ __forceinline__ void slot_step(
    int s, int cur, int nxt, int tid, int lane, int w, int gp, int t4,
    int ob, int oj, int jg, int bg0,
    const uint32_t (&Ahi)[16][4], const uint32_t (&Alo)[16][4],
    uint32_t* Hhi, uint32_t* Hlo, float* d_sm,
    float pv, float sv, float on_mid, float on_end,
    float& ccar, float& hcar,
    float Gi, float Gf, float Gg, float Go, float tt,
    float* __restrict__ out)
{
    // stage packed h -> SMEM hi/lo pair arrays (L2-coherent loads)
    {
        const uint4* src = reinterpret_cast<const uint4*>(
            &g_hpack[cur][(bg0 + w) * H_ + lane * 8]);
        uint4 p0 = ldcg_u4(src), p1 = ldcg_u4(src + 1);
        const int dst = w * 132 + lane * 4;
        Hhi[dst + 0] = __byte_perm(p0.x, p0.y, 0x5410);
        Hlo[dst + 0] = __byte_perm(p0.x, p0.y, 0x7632);
        Hhi[dst + 1] = __byte_perm(p0.z, p0.w, 0x5410);
        Hlo[dst + 1] = __byte_perm(p0.z, p0.w, 0x7632);
        Hhi[dst + 2] = __byte_perm(p1.x, p1.y, 0x5410);
        Hlo[dst + 2] = __byte_perm(p1.x, p1.y, 0x7632);
        Hhi[dst + 3] = __byte_perm(p1.z, p1.w, 0x5410);
        Hlo[dst + 3] = __byte_perm(p1.z, p1.w, 0x7632);
    }
    __syncthreads();

    // MMA: D[16w..16w+16, 8 batches], K=256, 3 independent chains
    float4 Da = make_float4(0.f, 0.f, 0.f, 0.f);
    float4 Db = make_float4(0.f, 0.f, 0.f, 0.f);
    float4 Dc = make_float4(0.f, 0.f, 0.f, 0.f);
#pragma unroll
    for (int q = 0; q < 16; q++) {
        const int base = gp * 132 + q * 8 + t4;
        uint32_t bh0 = Hhi[base], bh1 = Hhi[base + 4];
        uint32_t bl0 = Hlo[base], bl1 = Hlo[base + 4];
        mma_bf16(Da, Ahi[q], bh0, bh1);
        mma_bf16(Db, Ahi[q], bl0, bl1);
        mma_bf16(Dc, Alo[q], bh0, bh1);
    }
    float4 D = make_float4(Da.x + Db.x + Dc.x, Da.y + Db.y + Dc.y,
                           Da.z + Db.z + Dc.z, Da.w + Db.w + Dc.w);
    {
        const int r0 = 16 * w + gp;
        d_sm[r0 * 10 + 2 * t4] = D.x;
        d_sm[r0 * 10 + 2 * t4 + 1] = D.y;
        d_sm[(r0 + 8) * 10 + 2 * t4] = D.z;
        d_sm[(r0 + 8) * 10 + 2 * t4 + 1] = D.w;
    }
    __syncthreads();

    // cell
    float p0 = d_sm[(0 * 32 + oj) * 10 + ob];
    float p1 = d_sm[(1 * 32 + oj) * 10 + ob];
    float p2 = d_sm[(2 * 32 + oj) * 10 + ob];
    float p3 = d_sm[(3 * 32 + oj) * 10 + ob];

    float it = sigf(Gi + p0);
    float ft = sigf(Gf + p1);
    float gt = tanhf(Gg + p2);
    float ot = sigf(Go + p3);
    float cn = ft * ccar + it * gt;
    float hn = ot * tanhf(cn);

    float ic = fmodf(tt + sv, pv);
    float mask;
    if (ic <= on_mid)      mask = ic / on_mid;
    else if (ic <= on_end) mask = (on_end - ic) / on_mid;
    else                   mask = OFF_SLOPE * (ic / pv);

    ccar = mask * cn + (1.f - mask) * ccar;
    float h2 = mask * hn + (1.f - mask) * hcar;
    hcar = h2;

    // publish packed h + output
    __nv_bfloat16 hb = __float2bfloat16(h2);
    __nv_bfloat16 lb = __float2bfloat16(h2 - __bfloat162float(hb));
    g_hpack[nxt][(bg0 + ob) * H_ + jg] =
        (uint32_t)__bfloat16_as_ushort(hb) |
        ((uint32_t)__bfloat16_as_ushort(lb) << 16);
    out[((size_t)(bg0 + ob) * S_ + s) * H_ + jg] = h2;
}

// 64 CTAs = 8 group-pairs x 8 h-slices. Each CTA serves TWO groups (A, B)
// temporally interleaved: B's compute hides A's barrier latency and vice
// versa (staggered polls). U frags shared by both slots.
__global__ __launch_bounds__(256, 1) void plstm_rec(
    const float* __restrict__ U, const float* __restrict__ ts,
    const float* __restrict__ Per, const float* __restrict__ Shf,
    const float* __restrict__ Oe, float* __restrict__ out, int writeTails) {
    __shared__ __align__(16) uint32_t Hhi[8 * 132];
    __shared__ __align__(16) uint32_t Hlo[8 * 132];
    __shared__ __align__(16) float d_sm[128 * 10];

    const int tid = threadIdx.x;
    const int lane = tid & 31;
    const int w = tid >> 5;
    const int gp = lane >> 2;
    const int t4 = lane & 3;
    const int pr = blockIdx.x >> 3;         // group pair 0..7
    const int hslc = blockIdx.x & 7;
    const int bg0A = pr * 16;               // group A batches
    const int bg0B = pr * 16 + 8;           // group B batches
    const int hs = hslc * 32;
    const int ob = w;
    const int oj = lane;
    const int jg = hs + oj;
    unsigned* cntA = &g_cnt[2 * pr];
    unsigned* cntB = &g_cnt[2 * pr + 1];

    const float pv = fabsf(Per[jg]);
    const float sv = Shf[jg];
    const float oe = fabsf(Oe[jg]);
    const float on_end = oe * pv;
    const float on_mid = (oe * 0.5f) * pv;

    // one-time: preload U^T fragments (hi/lo bf16 split) — shared by slots
    uint32_t Ahi[16][4], Alo[16][4];
    {
        const int gblk = w >> 1;
        const int u0 = (w & 1) * 16;
        const int gc0 = gblk * 256 + hs + u0 + gp;
        const int gc1 = gc0 + 8;
#pragma unroll
        for (int q = 0; q < 16; q++) {
            const int k0 = q * 16 + 2 * t4;
            float x, y;
            x = U[(size_t)k0 * 1024 + gc0];       y = U[(size_t)(k0 + 1) * 1024 + gc0];
            split_pack(x, y, Ahi[q][0], Alo[q][0]);
            x = U[(size_t)k0 * 1024 + gc1];       y = U[(size_t)(k0 + 1) * 1024 + gc1];
            split_pack(x, y, Ahi[q][1], Alo[q][1]);
            x = U[(size_t)(k0 + 8) * 1024 + gc0]; y = U[(size_t)(k0 + 9) * 1024 + gc0];
            split_pack(x, y, Ahi[q][2], Alo[q][2]);
            x = U[(size_t)(k0 + 8) * 1024 + gc1]; y = U[(size_t)(k0 + 9) * 1024 + gc1];
            split_pack(x, y, Ahi[q][3], Alo[q][3]);
        }
    }

    float ccarA = 0.f, hcarA = 0.f, ccarB = 0.f, hcarB = 0.f;
    const float* tsA = ts + (size_t)(bg0A + ob) * S_;
    const float* tsB = ts + (size_t)(bg0B + ob) * S_;
    const float* GbA = g_G + (size_t)(bg0A + ob) * S_ * 1024 + hs + oj;
    const float* GbB = g_G + (size_t)(bg0B + ob) * S_ * 1024 + hs + oj;

    float GiA = GbA[0], GfA = GbA[256], GgA = GbA[512], GoA = GbA[768];
    float GiB = GbB[0], GfB = GbB[256], GgB = GbB[512], GoB = GbB[768];
    float ttA = tsA[0], ttB = tsB[0];

    for (int s = 0; s < S_; s++) {
        const int cur = s & 1, nxt = cur ^ 1;

        // ---- slot A, step s (A's barrier for s-1 polled at end of prev iter)
        slot_step(s, cur, nxt, tid, lane, w, gp, t4, ob, oj, jg, bg0A,
                  Ahi, Alo, Hhi, Hlo, d_sm, pv, sv, on_mid, on_end,
                  ccarA, hcarA, GiA, GfA, GgA, GoA, ttA, out);
        __syncthreads();                     // publishes done -> arrive
        if (tid == 0) red_release(cntA);

        // ---- poll B(s-1): settled during A's compute (one full slot ago)
        if (s > 0 && tid == 0) poll_ge(cntB, 8u * (unsigned)s);
        __syncthreads();

        // ---- slot B, step s
        slot_step(s, cur, nxt, tid, lane, w, gp, t4, ob, oj, jg, bg0B,
                  Ahi, Alo, Hhi, Hlo, d_sm, pv, sv, on_mid, on_end,
                  ccarB, hcarB, GiB, GfB, GgB, GoB, ttB, out);

        // next-step prefetch for both slots (in flight during barrier ops)
        if (s + 1 < S_) {
            const float* GpA = GbA + (size_t)(s + 1) * 1024;
            const float* GpB = GbB + (size_t)(s + 1) * 1024;
            GiA = GpA[0]; GfA = GpA[256]; GgA = GpA[512]; GoA = GpA[768];
            GiB = GpB[0]; GfB = GpB[256]; GgB = GpB[512]; GoB = GpB[768];
            ttA = tsA[s + 1]; ttB = tsB[s + 1];
        }

        __syncthreads();                     // publishes done -> arrive
        if (tid == 0) red_release(cntB);

        // ---- poll A(s): settled during B's compute
        if (tid == 0) poll_ge(cntA, 8u * (unsigned)(s + 1));
        __syncthreads();
    }

    if (writeTails) {
        const size_t baseT = (size_t)B_ * S_ * H_;
        out[baseT + (size_t)(bg0A + ob) * H_ + jg] = hcarA;
        out[baseT + (size_t)B_ * H_ + (size_t)(bg0A + ob) * H_ + jg] = ccarA;
        out[baseT + (size_t)(bg0B + ob) * H_ + jg] = hcarB;
        out[baseT + (size_t)B_ * H_ + (size_t)(bg0B + ob) * H_ + jg] = ccarB;
    }
}

// ---------------- launch ----------------
extern "C" void kernel_launch(void* const* d_in, const int* in_sizes, int n_in,
                              void* d_out, int out_size) {
    const float* x    = (const float*)d_in[0];
    const float* ts   = (const float*)d_in[1];
    const float* W    = (const float*)d_in[2];
    const float* U    = (const float*)d_in[3];
    const float* bias = (const float*)d_in[4];
    const float* Per  = (const float*)d_in[5];
    const float* Shf  = (const float*)d_in[6];
    const float* Oe   = (const float*)d_in[7];
    float* out = (float*)d_out;

    init_k<<<64, 256>>>();

    const int smA = 4 * 128 * 66 * 4;   // 135168 B dynamic SMEM
    cudaFuncSetAttribute(gemm_xw_mma, cudaFuncAttributeMaxDynamicSharedMemorySize, smA);
    dim3 gg(131072 / 128, 1024 / 128);
    gemm_xw_mma<<<gg, 256, smA>>>(x, W, bias);

    const long long need = (long long)B_ * S_ * H_ + 2LL * B_ * H_;
    int writeTails = ((long long)out_size >= need) ? 1 : 0;
    plstm_rec<<<64, 256>>>(U, ts, Per, Shf, Oe, out, writeTails);
}

// round 9
// speedup vs baseline: 1.6814x; 1.6814x over previous
#include <cuda_runtime.h>
#include <cuda_bf16.h>
#include <cstdint>

#define B_   128
#define S_   1024
#define I_   128
#define H_   256
#define OFF_SLOPE 0.001f

// ---------------- device scratch (static, no allocations) ----------------
__device__ __align__(16) float g_G[134217728];          // [B*S][1024] = 512 MB
__device__ __align__(16) unsigned g_hpack[2][B_ * H_];  // packed (bf16 hi | lo<<16)
__device__ __align__(128) unsigned g_cnt[16][32];       // 1 counter per 128B line

__device__ __forceinline__ void split_pack(float x, float y,
                                           uint32_t& hi, uint32_t& lo) {
    __nv_bfloat16 hx = __float2bfloat16(x);
    __nv_bfloat16 hy = __float2bfloat16(y);
    __nv_bfloat16 lx = __float2bfloat16(x - __bfloat162float(hx));
    __nv_bfloat16 ly = __float2bfloat16(y - __bfloat162float(hy));
    hi = (uint32_t)__bfloat16_as_ushort(hx) | ((uint32_t)__bfloat16_as_ushort(hy) << 16);
    lo = (uint32_t)__bfloat16_as_ushort(lx) | ((uint32_t)__bfloat16_as_ushort(ly) << 16);
}

__device__ __forceinline__ void mma_bf16(float4& d, const uint32_t* a,
                                         uint32_t b0, uint32_t b1) {
    asm volatile(
        "mma.sync.aligned.m16n8k16.row.col.f32.bf16.bf16.f32 "
        "{%0,%1,%2,%3}, {%4,%5,%6,%7}, {%8,%9}, {%0,%1,%2,%3};"
        : "+f"(d.x), "+f"(d.y), "+f"(d.z), "+f"(d.w)
        : "r"(a[0]), "r"(a[1]), "r"(a[2]), "r"(a[3]), "r"(b0), "r"(b1));
}

// ---------------- init ----------------
__global__ void init_k() {
    unsigned t = blockIdx.x * blockDim.x + threadIdx.x;
    if (t < 16 * 32) ((unsigned*)g_cnt)[t] = 0u;
    for (unsigned i = t; i < 2u * B_ * H_; i += gridDim.x * blockDim.x)
        ((unsigned*)g_hpack)[i] = 0u;
}

// ---------------- phase A: G = x @ W + bias (bf16x3 tensor-core GEMM) ----
__global__ __launch_bounds__(256) void gemm_xw_mma(const float* __restrict__ X,
                                                   const float* __restrict__ Wm,
                                                   const float* __restrict__ bias) {
    extern __shared__ uint32_t sm[];
    uint32_t* Axh = sm;
    uint32_t* Axl = Axh + 128 * 66;
    uint32_t* Bnh = Axl + 128 * 66;
    uint32_t* Bnl = Bnh + 128 * 66;

    const int m0 = blockIdx.x * 128;
    const int n0 = blockIdx.y * 128;
    const int tid = threadIdx.x;
    const int lane = tid & 31, w = tid >> 5;
    const int gp = lane >> 2, t4 = lane & 3;
    const int wm = w >> 1, wn = w & 1;

#pragma unroll
    for (int j = 0; j < 16; j++) {
        int lin = tid + j * 256;
        int m = lin >> 5, c = lin & 31;
        float4 v = reinterpret_cast<const float4*>(X)[(size_t)(m0 + m) * 32 + c];
        uint32_t h0, l0, h1, l1;
        split_pack(v.x, v.y, h0, l0);
        split_pack(v.z, v.w, h1, l1);
        Axh[m * 66 + 2 * c] = h0; Axh[m * 66 + 2 * c + 1] = h1;
        Axl[m * 66 + 2 * c] = l0; Axl[m * 66 + 2 * c + 1] = l1;
    }
    {
        const int n = tid & 127, kh = tid >> 7;
        const float* wp = Wm + (size_t)(kh * 64) * 1024 + n0 + n;
        uint32_t* dh = &Bnh[n * 66 + kh * 32];
        uint32_t* dl = &Bnl[n * 66 + kh * 32];
#pragma unroll
        for (int j = 0; j < 32; j++) {
            float a = wp[(size_t)(2 * j) * 1024];
            float b = wp[(size_t)(2 * j + 1) * 1024];
            uint32_t h, l; split_pack(a, b, h, l);
            dh[j] = h; dl[j] = l;
        }
    }
    __syncthreads();

    float4 acc[2][8];
#pragma unroll
    for (int mt = 0; mt < 2; mt++)
#pragma unroll
        for (int nt = 0; nt < 8; nt++) acc[mt][nt] = make_float4(0.f, 0.f, 0.f, 0.f);

#pragma unroll
    for (int ks = 0; ks < 8; ks++) {
        uint32_t ah[2][4], al[2][4];
#pragma unroll
        for (int mt = 0; mt < 2; mt++) {
            const int r0 = (wm * 32 + mt * 16 + gp) * 66 + ks * 8;
            ah[mt][0] = Axh[r0 + t4];       ah[mt][1] = Axh[r0 + 8 * 66 + t4];
            ah[mt][2] = Axh[r0 + t4 + 4];   ah[mt][3] = Axh[r0 + 8 * 66 + t4 + 4];
            al[mt][0] = Axl[r0 + t4];       al[mt][1] = Axl[r0 + 8 * 66 + t4];
            al[mt][2] = Axl[r0 + t4 + 4];   al[mt][3] = Axl[r0 + 8 * 66 + t4 + 4];
        }
#pragma unroll
        for (int nt = 0; nt < 8; nt++) {
            const int c0 = (wn * 64 + nt * 8 + gp) * 66 + ks * 8;
            uint32_t bh0 = Bnh[c0 + t4], bh1 = Bnh[c0 + t4 + 4];
            uint32_t bl0 = Bnl[c0 + t4], bl1 = Bnl[c0 + t4 + 4];
#pragma unroll
            for (int mt = 0; mt < 2; mt++) {
                mma_bf16(acc[mt][nt], ah[mt], bh0, bh1);
                mma_bf16(acc[mt][nt], ah[mt], bl0, bl1);
                mma_bf16(acc[mt][nt], al[mt], bh0, bh1);
            }
        }
    }

#pragma unroll
    for (int nt = 0; nt < 8; nt++) {
        const int n = n0 + wn * 64 + nt * 8 + 2 * t4;
        float2 bv = *reinterpret_cast<const float2*>(bias + n);
#pragma unroll
        for (int mt = 0; mt < 2; mt++) {
            const int m = m0 + wm * 32 + mt * 16 + gp;
            float4 d = acc[mt][nt];
            *reinterpret_cast<float2*>(&g_G[(size_t)m * 1024 + n]) =
                make_float2(d.x + bv.x, d.y + bv.y);
            *reinterpret_cast<float2*>(&g_G[(size_t)(m + 8) * 1024 + n]) =
                make_float2(d.z + bv.x, d.w + bv.y);
        }
    }
}

// ---------------- phase B: persistent recurrent kernel (HMMA) ------------
__device__ __forceinline__ float sigf(float x) { return 1.0f / (1.0f + __expf(-x)); }

__device__ __forceinline__ unsigned ld_acq(const unsigned* p) {
    unsigned v;
    asm volatile("ld.global.acquire.gpu.u32 %0, [%1];" : "=r"(v) : "l"(p) : "memory");
    return v;
}
__device__ __forceinline__ void red_release(unsigned* p) {
    unsigned one = 1u;
    asm volatile("red.release.gpu.global.add.u32 [%0], %1;" :: "l"(p), "r"(one) : "memory");
}
__device__ __forceinline__ uint4 ldcg_u4(const uint4* p) {
    uint4 v;
    asm volatile("ld.global.cg.v4.u32 {%0,%1,%2,%3}, [%4];"
                 : "=r"(v.x), "=r"(v.y), "=r"(v.z), "=r"(v.w) : "l"(p));
    return v;
}

// 128 CTAs = 16 groups (8 batches) x 8 slices (32 h-units = 128 gate rows).
// D[128 gates, 8 batches] = U^T_slice[128,256] @ h^T[256,8] via mma.sync
// bf16x3 with 3 independent accumulator chains. U frags register-resident.
// Per-group barrier counter padded to its own 128B L2 line (no cross-group
// line contention).
__global__ __launch_bounds__(256, 1) void plstm_rec(
    const float* __restrict__ U, const float* __restrict__ ts,
    const float* __restrict__ Per, const float* __restrict__ Shf,
    const float* __restrict__ Oe, float* __restrict__ out, int writeTails) {
    __shared__ __align__(16) uint32_t Hhi[8 * 132];
    __shared__ __align__(16) uint32_t Hlo[8 * 132];
    __shared__ __align__(16) float d_sm[128 * 10];

    const int tid = threadIdx.x;
    const int lane = tid & 31;
    const int w = tid >> 5;
    const int gp = lane >> 2;
    const int t4 = lane & 3;
    const int grp = blockIdx.x >> 3;
    const int hslc = blockIdx.x & 7;
    const int bg0 = grp * 8;
    const int hs = hslc * 32;
    const int ob = tid >> 5;
    const int oj = lane;
    const int jg = hs + oj;
    unsigned* cnt = &g_cnt[grp][0];

    const float pv = fabsf(Per[jg]);
    const float sv = Shf[jg];
    const float oe = fabsf(Oe[jg]);
    const float on_end = oe * pv;
    const float on_mid = (oe * 0.5f) * pv;

    // one-time: preload U^T fragments (hi/lo bf16 split)
    uint32_t Ahi[16][4], Alo[16][4];
    {
        const int gblk = w >> 1;
        const int u0 = (w & 1) * 16;
        const int gc0 = gblk * 256 + hs + u0 + gp;
        const int gc1 = gc0 + 8;
#pragma unroll
        for (int q = 0; q < 16; q++) {
            const int k0 = q * 16 + 2 * t4;
            float x, y;
            x = U[(size_t)k0 * 1024 + gc0];       y = U[(size_t)(k0 + 1) * 1024 + gc0];
            split_pack(x, y, Ahi[q][0], Alo[q][0]);
            x = U[(size_t)k0 * 1024 + gc1];       y = U[(size_t)(k0 + 1) * 1024 + gc1];
            split_pack(x, y, Ahi[q][1], Alo[q][1]);
            x = U[(size_t)(k0 + 8) * 1024 + gc0]; y = U[(size_t)(k0 + 9) * 1024 + gc0];
            split_pack(x, y, Ahi[q][2], Alo[q][2]);
            x = U[(size_t)(k0 + 8) * 1024 + gc1]; y = U[(size_t)(k0 + 9) * 1024 + gc1];
            split_pack(x, y, Ahi[q][3], Alo[q][3]);
        }
    }

    float ccar = 0.f, hcar = 0.f;
    const float* tsrow = ts + (size_t)(bg0 + ob) * S_;
    const float* Gbase = g_G + (size_t)(bg0 + ob) * S_ * 1024 + hs + oj;

    float Gi = Gbase[0], Gf = Gbase[256], Gg = Gbase[512], Go = Gbase[768];
    float tt = tsrow[0];

    for (int s = 0; s < S_; s++) {
        const int cur = s & 1, nxt = cur ^ 1;

        // stage packed h -> SMEM hi/lo pair arrays (L2-coherent loads)
        {
            const uint4* src = reinterpret_cast<const uint4*>(
                &g_hpack[cur][(bg0 + w) * H_ + lane * 8]);
            uint4 p0 = ldcg_u4(src), p1 = ldcg_u4(src + 1);
            const int dst = w * 132 + lane * 4;
            Hhi[dst + 0] = __byte_perm(p0.x, p0.y, 0x5410);
            Hlo[dst + 0] = __byte_perm(p0.x, p0.y, 0x7632);
            Hhi[dst + 1] = __byte_perm(p0.z, p0.w, 0x5410);
            Hlo[dst + 1] = __byte_perm(p0.z, p0.w, 0x7632);
            Hhi[dst + 2] = __byte_perm(p1.x, p1.y, 0x5410);
            Hlo[dst + 2] = __byte_perm(p1.x, p1.y, 0x7632);
            Hhi[dst + 3] = __byte_perm(p1.z, p1.w, 0x5410);
            Hlo[dst + 3] = __byte_perm(p1.z, p1.w, 0x7632);
        }
        __syncthreads();

        // MMA with 3 independent accumulator chains
        float4 Da = make_float4(0.f, 0.f, 0.f, 0.f);
        float4 Db = make_float4(0.f, 0.f, 0.f, 0.f);
        float4 Dc = make_float4(0.f, 0.f, 0.f, 0.f);
#pragma unroll
        for (int q = 0; q < 16; q++) {
            const int base = gp * 132 + q * 8 + t4;
            uint32_t bh0 = Hhi[base], bh1 = Hhi[base + 4];
            uint32_t bl0 = Hlo[base], bl1 = Hlo[base + 4];
            mma_bf16(Da, Ahi[q], bh0, bh1);
            mma_bf16(Db, Ahi[q], bl0, bl1);
            mma_bf16(Dc, Alo[q], bh0, bh1);
        }
        float4 D = make_float4(Da.x + Db.x + Dc.x, Da.y + Db.y + Dc.y,
                               Da.z + Db.z + Dc.z, Da.w + Db.w + Dc.w);

        {
            const int r0 = 16 * w + gp;
            d_sm[r0 * 10 + 2 * t4] = D.x;
            d_sm[r0 * 10 + 2 * t4 + 1] = D.y;
            d_sm[(r0 + 8) * 10 + 2 * t4] = D.z;
            d_sm[(r0 + 8) * 10 + 2 * t4 + 1] = D.w;
        }
        __syncthreads();

        float p0 = d_sm[(0 * 32 + oj) * 10 + ob];
        float p1 = d_sm[(1 * 32 + oj) * 10 + ob];
        float p2 = d_sm[(2 * 32 + oj) * 10 + ob];
        float p3 = d_sm[(3 * 32 + oj) * 10 + ob];

        float it = sigf(Gi + p0);
        float ft = sigf(Gf + p1);
        float gt = tanhf(Gg + p2);
        float ot = sigf(Go + p3);
        float cn = ft * ccar + it * gt;
        float hn = ot * tanhf(cn);

        float ic = fmodf(tt + sv, pv);
        float mask;
        if (ic <= on_mid)      mask = ic / on_mid;
        else if (ic <= on_end) mask = (on_end - ic) / on_mid;
        else                   mask = OFF_SLOPE * (ic / pv);

        ccar = mask * cn + (1.f - mask) * ccar;
        float h2 = mask * hn + (1.f - mask) * hcar;
        hcar = h2;

        // publish packed h + output
        {
            __nv_bfloat16 hb = __float2bfloat16(h2);
            __nv_bfloat16 lb = __float2bfloat16(h2 - __bfloat162float(hb));
            g_hpack[nxt][(bg0 + ob) * H_ + jg] =
                (uint32_t)__bfloat16_as_ushort(hb) |
                ((uint32_t)__bfloat16_as_ushort(lb) << 16);
        }
        out[((size_t)(bg0 + ob) * S_ + s) * H_ + jg] = h2;

        // next-step prefetch launched BEFORE the barrier (in flight during wait)
        if (s + 1 < S_) {
            const float* Gp = Gbase + (size_t)(s + 1) * 1024;
            Gi = Gp[0]; Gf = Gp[256]; Gg = Gp[512]; Go = Gp[768];
            tt = tsrow[s + 1];
        }

        // group barrier: release-arrive (no return trip) + acquire-poll
        __syncthreads();
        if (tid == 0) {
            red_release(cnt);
            const unsigned tgt = 8u * (unsigned)(s + 1);
            while (ld_acq(cnt) < tgt) {}
        }
        __syncthreads();
    }

    if (writeTails) {
        const size_t baseT = (size_t)B_ * S_ * H_;
        out[baseT + (size_t)(bg0 + ob) * H_ + jg] = hcar;                    // h_T
        out[baseT + (size_t)B_ * H_ + (size_t)(bg0 + ob) * H_ + jg] = ccar;  // c_T
    }
}

// ---------------- launch ----------------
extern "C" void kernel_launch(void* const* d_in, const int* in_sizes, int n_in,
                              void* d_out, int out_size) {
    const float* x    = (const float*)d_in[0];
    const float* ts   = (const float*)d_in[1];
    const float* W    = (const float*)d_in[2];
    const float* U    = (const float*)d_in[3];
    const float* bias = (const float*)d_in[4];
    const float* Per  = (const float*)d_in[5];
    const float* Shf  = (const float*)d_in[6];
    const float* Oe   = (const float*)d_in[7];
    float* out = (float*)d_out;

    init_k<<<64, 256>>>();

    const int smA = 4 * 128 * 66 * 4;   // 135168 B dynamic SMEM
    cudaFuncSetAttribute(gemm_xw_mma, cudaFuncAttributeMaxDynamicSharedMemorySize, smA);
    dim3 gg(131072 / 128, 1024 / 128);
    gemm_xw_mma<<<gg, 256, smA>>>(x, W, bias);

    const long long need = (long long)B_ * S_ * H_ + 2LL * B_ * H_;
    int writeTails = ((long long)out_size >= need) ? 1 : 0;
    plstm_rec<<<128, 256>>>(U, ts, Per, Shf, Oe, out, writeTails);
}

// round 10
// speedup vs baseline: 1.7001x; 1.0111x over previous
#include <cuda_runtime.h>
#include <cuda_bf16.h>
#include <cstdint>

#define B_   128
#define S_   1024
#define I_   128
#define H_   256
#define OFF_SLOPE 0.001f

// ---------------- device scratch (static, no allocations) ----------------
__device__ __align__(16) float g_G[134217728];          // [B*S][1024] = 512 MB
__device__ __align__(16) unsigned g_hpack[2][B_ * H_];  // packed (bf16 hi | lo<<16)
__device__ __align__(128) unsigned g_flag[16][8][32];   // [grp][cta], own 128B line

__device__ __forceinline__ void split_pack(float x, float y,
                                           uint32_t& hi, uint32_t& lo) {
    __nv_bfloat16 hx = __float2bfloat16(x);
    __nv_bfloat16 hy = __float2bfloat16(y);
    __nv_bfloat16 lx = __float2bfloat16(x - __bfloat162float(hx));
    __nv_bfloat16 ly = __float2bfloat16(y - __bfloat162float(hy));
    hi = (uint32_t)__bfloat16_as_ushort(hx) | ((uint32_t)__bfloat16_as_ushort(hy) << 16);
    lo = (uint32_t)__bfloat16_as_ushort(lx) | ((uint32_t)__bfloat16_as_ushort(ly) << 16);
}

__device__ __forceinline__ void mma_bf16(float4& d, const uint32_t* a,
                                         uint32_t b0, uint32_t b1) {
    asm volatile(
        "mma.sync.aligned.m16n8k16.row.col.f32.bf16.bf16.f32 "
        "{%0,%1,%2,%3}, {%4,%5,%6,%7}, {%8,%9}, {%0,%1,%2,%3};"
        : "+f"(d.x), "+f"(d.y), "+f"(d.z), "+f"(d.w)
        : "r"(a[0]), "r"(a[1]), "r"(a[2]), "r"(a[3]), "r"(b0), "r"(b1));
}

// ---------------- init ----------------
__global__ void init_k() {
    unsigned t = blockIdx.x * blockDim.x + threadIdx.x;
    if (t < 16u * 8u * 32u) ((unsigned*)g_flag)[t] = 0u;
    for (unsigned i = t; i < 2u * B_ * H_; i += gridDim.x * blockDim.x)
        ((unsigned*)g_hpack)[i] = 0u;
}

// ---------------- phase A: G = x @ W + bias (bf16x3 tensor-core GEMM) ----
__global__ __launch_bounds__(256) void gemm_xw_mma(const float* __restrict__ X,
                                                   const float* __restrict__ Wm,
                                                   const float* __restrict__ bias) {
    extern __shared__ uint32_t sm[];
    uint32_t* Axh = sm;
    uint32_t* Axl = Axh + 128 * 66;
    uint32_t* Bnh = Axl + 128 * 66;
    uint32_t* Bnl = Bnh + 128 * 66;

    const int m0 = blockIdx.x * 128;
    const int n0 = blockIdx.y * 128;
    const int tid = threadIdx.x;
    const int lane = tid & 31, w = tid >> 5;
    const int gp = lane >> 2, t4 = lane & 3;
    const int wm = w >> 1, wn = w & 1;

#pragma unroll
    for (int j = 0; j < 16; j++) {
        int lin = tid + j * 256;
        int m = lin >> 5, c = lin & 31;
        float4 v = reinterpret_cast<const float4*>(X)[(size_t)(m0 + m) * 32 + c];
        uint32_t h0, l0, h1, l1;
        split_pack(v.x, v.y, h0, l0);
        split_pack(v.z, v.w, h1, l1);
        Axh[m * 66 + 2 * c] = h0; Axh[m * 66 + 2 * c + 1] = h1;
        Axl[m * 66 + 2 * c] = l0; Axl[m * 66 + 2 * c + 1] = l1;
    }
    {
        const int n = tid & 127, kh = tid >> 7;
        const float* wp = Wm + (size_t)(kh * 64) * 1024 + n0 + n;
        uint32_t* dh = &Bnh[n * 66 + kh * 32];
        uint32_t* dl = &Bnl[n * 66 + kh * 32];
#pragma unroll
        for (int j = 0; j < 32; j++) {
            float a = wp[(size_t)(2 * j) * 1024];
            float b = wp[(size_t)(2 * j + 1) * 1024];
            uint32_t h, l; split_pack(a, b, h, l);
            dh[j] = h; dl[j] = l;
        }
    }
    __syncthreads();

    float4 acc[2][8];
#pragma unroll
    for (int mt = 0; mt < 2; mt++)
#pragma unroll
        for (int nt = 0; nt < 8; nt++) acc[mt][nt] = make_float4(0.f, 0.f, 0.f, 0.f);

#pragma unroll
    for (int ks = 0; ks < 8; ks++) {
        uint32_t ah[2][4], al[2][4];
#pragma unroll
        for (int mt = 0; mt < 2; mt++) {
            const int r0 = (wm * 32 + mt * 16 + gp) * 66 + ks * 8;
            ah[mt][0] = Axh[r0 + t4];       ah[mt][1] = Axh[r0 + 8 * 66 + t4];
            ah[mt][2] = Axh[r0 + t4 + 4];   ah[mt][3] = Axh[r0 + 8 * 66 + t4 + 4];
            al[mt][0] = Axl[r0 + t4];       al[mt][1] = Axl[r0 + 8 * 66 + t4];
            al[mt][2] = Axl[r0 + t4 + 4];   al[mt][3] = Axl[r0 + 8 * 66 + t4 + 4];
        }
#pragma unroll
        for (int nt = 0; nt < 8; nt++) {
            const int c0 = (wn * 64 + nt * 8 + gp) * 66 + ks * 8;
            uint32_t bh0 = Bnh[c0 + t4], bh1 = Bnh[c0 + t4 + 4];
            uint32_t bl0 = Bnl[c0 + t4], bl1 = Bnl[c0 + t4 + 4];
#pragma unroll
            for (int mt = 0; mt < 2; mt++) {
                mma_bf16(acc[mt][nt], ah[mt], bh0, bh1);
                mma_bf16(acc[mt][nt], ah[mt], bl0, bl1);
                mma_bf16(acc[mt][nt], al[mt], bh0, bh1);
            }
        }
    }

#pragma unroll
    for (int nt = 0; nt < 8; nt++) {
        const int n = n0 + wn * 64 + nt * 8 + 2 * t4;
        float2 bv = *reinterpret_cast<const float2*>(bias + n);
#pragma unroll
        for (int mt = 0; mt < 2; mt++) {
            const int m = m0 + wm * 32 + mt * 16 + gp;
            float4 d = acc[mt][nt];
            *reinterpret_cast<float2*>(&g_G[(size_t)m * 1024 + n]) =
                make_float2(d.x + bv.x, d.y + bv.y);
            *reinterpret_cast<float2*>(&g_G[(size_t)(m + 8) * 1024 + n]) =
                make_float2(d.z + bv.x, d.w + bv.y);
        }
    }
}

// ---------------- phase B: persistent recurrent kernel (HMMA) ------------
__device__ __forceinline__ float sigf(float x) { return 1.0f / (1.0f + __expf(-x)); }

__device__ __forceinline__ unsigned ld_acq(const unsigned* p) {
    unsigned v;
    asm volatile("ld.global.acquire.gpu.u32 %0, [%1];" : "=r"(v) : "l"(p) : "memory");
    return v;
}
__device__ __forceinline__ void st_release(unsigned* p, unsigned v) {
    asm volatile("st.release.gpu.global.u32 [%0], %1;" :: "l"(p), "r"(v) : "memory");
}
__device__ __forceinline__ uint2 ldcg_u2(const uint2* p) {
    uint2 v;
    asm volatile("ld.global.cg.v2.u32 {%0,%1}, [%2];"
                 : "=r"(v.x), "=r"(v.y) : "l"(p));
    return v;
}

// 128 CTAs = 16 groups (8 batches) x 8 slices (32 h-units = 128 gate rows).
// Fine-grained h exchange: producer CTA (grp,c) publishes unit-chunk c and
// release-stores flag[grp][c]=s+1; consumer WARP c polls only that flag and
// stages chunk c immediately (poll/stage pipelined across producers).
__global__ __launch_bounds__(256, 1) void plstm_rec(
    const float* __restrict__ U, const float* __restrict__ ts,
    const float* __restrict__ Per, const float* __restrict__ Shf,
    const float* __restrict__ Oe, float* __restrict__ out, int writeTails) {
    __shared__ __align__(16) uint32_t Hhi[8 * 132];
    __shared__ __align__(16) uint32_t Hlo[8 * 132];
    __shared__ __align__(16) float d_sm[128 * 10];

    const int tid = threadIdx.x;
    const int lane = tid & 31;
    const int w = tid >> 5;
    const int gp = lane >> 2;
    const int t4 = lane & 3;
    const int grp = blockIdx.x >> 3;
    const int hslc = blockIdx.x & 7;
    const int bg0 = grp * 8;
    const int hs = hslc * 32;
    const int ob = tid >> 5;
    const int oj = lane;
    const int jg = hs + oj;

    const float pv = fabsf(Per[jg]);
    const float sv = Shf[jg];
    const float oe = fabsf(Oe[jg]);
    const float on_end = oe * pv;
    const float on_mid = (oe * 0.5f) * pv;

    // one-time: preload U^T fragments (hi/lo bf16 split)
    uint32_t Ahi[16][4], Alo[16][4];
    {
        const int gblk = w >> 1;
        const int u0 = (w & 1) * 16;
        const int gc0 = gblk * 256 + hs + u0 + gp;
        const int gc1 = gc0 + 8;
#pragma unroll
        for (int q = 0; q < 16; q++) {
            const int k0 = q * 16 + 2 * t4;
            float x, y;
            x = U[(size_t)k0 * 1024 + gc0];       y = U[(size_t)(k0 + 1) * 1024 + gc0];
            split_pack(x, y, Ahi[q][0], Alo[q][0]);
            x = U[(size_t)k0 * 1024 + gc1];       y = U[(size_t)(k0 + 1) * 1024 + gc1];
            split_pack(x, y, Ahi[q][1], Alo[q][1]);
            x = U[(size_t)(k0 + 8) * 1024 + gc0]; y = U[(size_t)(k0 + 9) * 1024 + gc0];
            split_pack(x, y, Ahi[q][2], Alo[q][2]);
            x = U[(size_t)(k0 + 8) * 1024 + gc1]; y = U[(size_t)(k0 + 9) * 1024 + gc1];
            split_pack(x, y, Ahi[q][3], Alo[q][3]);
        }
    }

    float ccar = 0.f, hcar = 0.f;
    const float* tsrow = ts + (size_t)(bg0 + ob) * S_;
    const float* Gbase = g_G + (size_t)(bg0 + ob) * S_ * 1024 + hs + oj;

    float Gi = Gbase[0], Gf = Gbase[256], Gg = Gbase[512], Go = Gbase[768];
    float tt = tsrow[0];

    for (int s = 0; s < S_; s++) {
        const int cur = s & 1, nxt = cur ^ 1;

        // ---- fine-grained: warp w polls producer w's flag, stages chunk w
        if (s > 0) {
            if (lane == 0) {
                const unsigned tgt = (unsigned)s;
                while (ld_acq(&g_flag[grp][w][0]) < tgt) {}
            }
            __syncwarp();
        }
        // stage chunk w: units [32w, 32w+32) for 8 batches -> pair words
        {
            const int p = lane & 15;         // pair index within chunk
#pragma unroll
            for (int i = 0; i < 4; i++) {
                const int b = 2 * i + (lane >> 4);
                uint2 u = ldcg_u2(reinterpret_cast<const uint2*>(
                    &g_hpack[cur][(bg0 + b) * H_ + 32 * w + 2 * p]));
                const int dst = b * 132 + 16 * w + p;
                Hhi[dst] = __byte_perm(u.x, u.y, 0x5410);
                Hlo[dst] = __byte_perm(u.x, u.y, 0x7632);
            }
        }
        __syncthreads();

        // MMA with 3 independent accumulator chains
        float4 Da = make_float4(0.f, 0.f, 0.f, 0.f);
        float4 Db = make_float4(0.f, 0.f, 0.f, 0.f);
        float4 Dc = make_float4(0.f, 0.f, 0.f, 0.f);
#pragma unroll
        for (int q = 0; q < 16; q++) {
            const int base = gp * 132 + q * 8 + t4;
            uint32_t bh0 = Hhi[base], bh1 = Hhi[base + 4];
            uint32_t bl0 = Hlo[base], bl1 = Hlo[base + 4];
            mma_bf16(Da, Ahi[q], bh0, bh1);
            mma_bf16(Db, Ahi[q], bl0, bl1);
            mma_bf16(Dc, Alo[q], bh0, bh1);
        }
        float4 D = make_float4(Da.x + Db.x + Dc.x, Da.y + Db.y + Dc.y,
                               Da.z + Db.z + Dc.z, Da.w + Db.w + Dc.w);

        {
            const int r0 = 16 * w + gp;
            d_sm[r0 * 10 + 2 * t4] = D.x;
            d_sm[r0 * 10 + 2 * t4 + 1] = D.y;
            d_sm[(r0 + 8) * 10 + 2 * t4] = D.z;
            d_sm[(r0 + 8) * 10 + 2 * t4 + 1] = D.w;
        }
        __syncthreads();

        float p0 = d_sm[(0 * 32 + oj) * 10 + ob];
        float p1 = d_sm[(1 * 32 + oj) * 10 + ob];
        float p2 = d_sm[(2 * 32 + oj) * 10 + ob];
        float p3 = d_sm[(3 * 32 + oj) * 10 + ob];

        float it = sigf(Gi + p0);
        float ft = sigf(Gf + p1);
        float gt = tanhf(Gg + p2);
        float ot = sigf(Go + p3);
        float cn = ft * ccar + it * gt;
        float hn = ot * tanhf(cn);

        float ic = fmodf(tt + sv, pv);
        float mask;
        if (ic <= on_mid)      mask = ic / on_mid;
        else if (ic <= on_end) mask = (on_end - ic) / on_mid;
        else                   mask = OFF_SLOPE * (ic / pv);

        ccar = mask * cn + (1.f - mask) * ccar;
        float h2 = mask * hn + (1.f - mask) * hcar;
        hcar = h2;

        // publish packed h
        __nv_bfloat16 hb = __float2bfloat16(h2);
        __nv_bfloat16 lb = __float2bfloat16(h2 - __bfloat162float(hb));
        g_hpack[nxt][(bg0 + ob) * H_ + jg] =
            (uint32_t)__bfloat16_as_ushort(hb) |
            ((uint32_t)__bfloat16_as_ushort(lb) << 16);

        // next-step prefetch (in flight during flag propagation)
        if (s + 1 < S_) {
            const float* Gp = Gbase + (size_t)(s + 1) * 1024;
            Gi = Gp[0]; Gf = Gp[256]; Gg = Gp[512]; Go = Gp[768];
            tt = tsrow[s + 1];
        }

        // all 8 warps' publishes done -> release our flag
        __syncthreads();
        if (tid == 0) st_release(&g_flag[grp][hslc][0], (unsigned)(s + 1));

        // off critical path: output store
        out[((size_t)(bg0 + ob) * S_ + s) * H_ + jg] = h2;
    }

    if (writeTails) {
        const size_t baseT = (size_t)B_ * S_ * H_;
        out[baseT + (size_t)(bg0 + ob) * H_ + jg] = hcar;                    // h_T
        out[baseT + (size_t)B_ * H_ + (size_t)(bg0 + ob) * H_ + jg] = ccar;  // c_T
    }
}

// ---------------- launch ----------------
extern "C" void kernel_launch(void* const* d_in, const int* in_sizes, int n_in,
                              void* d_out, int out_size) {
    const float* x    = (const float*)d_in[0];
    const float* ts   = (const float*)d_in[1];
    const float* W    = (const float*)d_in[2];
    const float* U    = (const float*)d_in[3];
    const float* bias = (const float*)d_in[4];
    const float* Per  = (const float*)d_in[5];
    const float* Shf  = (const float*)d_in[6];
    const float* Oe   = (const float*)d_in[7];
    float* out = (float*)d_out;

    init_k<<<64, 256>>>();

    const int smA = 4 * 128 * 66 * 4;   // 135168 B dynamic SMEM
    cudaFuncSetAttribute(gemm_xw_mma, cudaFuncAttributeMaxDynamicSharedMemorySize, smA);
    dim3 gg(131072 / 128, 1024 / 128);
    gemm_xw_mma<<<gg, 256, smA>>>(x, W, bias);

    const long long need = (long long)B_ * S_ * H_ + 2LL * B_ * H_;
    int writeTails = ((long long)out_size >= need) ? 1 : 0;
    plstm_rec<<<128, 256>>>(U, ts, Per, Shf, Oe, out, writeTails);
}

// round 11
// speedup vs baseline: 2.0107x; 1.1827x over previous
#include <cuda_runtime.h>
#include <cuda_bf16.h>
#include <cstdint>

#define B_   128
#define S_   1024
#define I_   128
#define H_   256
#define OFF_SLOPE 0.001f

// ---------------- device scratch (static, no allocations) ----------------
__device__ __align__(16) unsigned g_hpack[2][B_ * H_];  // packed (bf16 hi | lo<<16)
__device__ __align__(128) unsigned g_flag[16][8][32];   // [grp][cta], own 128B line

__device__ __forceinline__ void split_pack(float x, float y,
                                           uint32_t& hi, uint32_t& lo) {
    __nv_bfloat16 hx = __float2bfloat16(x);
    __nv_bfloat16 hy = __float2bfloat16(y);
    __nv_bfloat16 lx = __float2bfloat16(x - __bfloat162float(hx));
    __nv_bfloat16 ly = __float2bfloat16(y - __bfloat162float(hy));
    hi = (uint32_t)__bfloat16_as_ushort(hx) | ((uint32_t)__bfloat16_as_ushort(hy) << 16);
    lo = (uint32_t)__bfloat16_as_ushort(lx) | ((uint32_t)__bfloat16_as_ushort(ly) << 16);
}

__device__ __forceinline__ void mma_bf16(float4& d, const uint32_t* a,
                                         uint32_t b0, uint32_t b1) {
    asm volatile(
        "mma.sync.aligned.m16n8k16.row.col.f32.bf16.bf16.f32 "
        "{%0,%1,%2,%3}, {%4,%5,%6,%7}, {%8,%9}, {%0,%1,%2,%3};"
        : "+f"(d.x), "+f"(d.y), "+f"(d.z), "+f"(d.w)
        : "r"(a[0]), "r"(a[1]), "r"(a[2]), "r"(a[3]), "r"(b0), "r"(b1));
}

// ---------------- init: zero flags + h0 ----------------
__global__ void init_k() {
    unsigned t = blockIdx.x * blockDim.x + threadIdx.x;
    if (t < 16u * 8u * 32u) ((unsigned*)g_flag)[t] = 0u;
    for (unsigned i = t; i < 2u * B_ * H_; i += gridDim.x * blockDim.x)
        ((unsigned*)g_hpack)[i] = 0u;
}

// ---------------- fused persistent PLSTM kernel --------------------------
// 128 CTAs = 16 groups (8 batches) x 8 slices (32 h-units = 128 gate rows).
// Per step: D[128 gates, 8 b] = [U^T | W^T][128,384] @ [h ; x_t][384,8]
// via mma.sync bf16x3 (K = 256 h + 128 x). No G materialization; bias in
// registers. x_t prefetched one step ahead (recurrence-independent).
__device__ __forceinline__ float sigf(float x) { return 1.0f / (1.0f + __expf(-x)); }

__device__ __forceinline__ unsigned ld_acq(const unsigned* p) {
    unsigned v;
    asm volatile("ld.global.acquire.gpu.u32 %0, [%1];" : "=r"(v) : "l"(p) : "memory");
    return v;
}
__device__ __forceinline__ void st_release(unsigned* p, unsigned v) {
    asm volatile("st.release.gpu.global.u32 [%0], %1;" :: "l"(p), "r"(v) : "memory");
}
__device__ __forceinline__ uint2 ldcg_u2(const uint2* p) {
    uint2 v;
    asm volatile("ld.global.cg.v2.u32 {%0,%1}, [%2];"
                 : "=r"(v.x), "=r"(v.y) : "l"(p));
    return v;
}

#define RPITCH 196   // SMEM row pitch (u32 pairs): 128 h + 64 x + pad

__global__ __launch_bounds__(256, 1) void plstm_rec(
    const float* __restrict__ X, const float* __restrict__ U,
    const float* __restrict__ Wm, const float* __restrict__ bias,
    const float* __restrict__ ts, const float* __restrict__ Per,
    const float* __restrict__ Shf, const float* __restrict__ Oe,
    float* __restrict__ out, int writeTails) {
    __shared__ __align__(16) uint32_t Hhi[8 * RPITCH];
    __shared__ __align__(16) uint32_t Hlo[8 * RPITCH];
    __shared__ __align__(16) float d_sm[128 * 10];

    const int tid = threadIdx.x;
    const int lane = tid & 31;
    const int w = tid >> 5;
    const int gp = lane >> 2;
    const int t4 = lane & 3;
    const int grp = blockIdx.x >> 3;
    const int hslc = blockIdx.x & 7;
    const int bg0 = grp * 8;
    const int hs = hslc * 32;
    const int ob = tid >> 5;
    const int oj = lane;
    const int jg = hs + oj;

    const float pv = fabsf(Per[jg]);
    const float sv = Shf[jg];
    const float oe = fabsf(Oe[jg]);
    const float on_end = oe * pv;
    const float on_mid = (oe * 0.5f) * pv;

    // owner bias registers (replace G prefetch)
    const float Bi = bias[jg], Bf = bias[256 + jg];
    const float Bg = bias[512 + jg], Bo = bias[768 + jg];

    // one-time: preload A^T fragments, q 0..15 = U (K 0..255),
    // q 16..23 = W (K 256..383). hi/lo bf16 split.
    uint32_t Ahi[24][4], Alo[24][4];
    {
        const int gblk = w >> 1;
        const int u0 = (w & 1) * 16;
        const int gc0 = gblk * 256 + hs + u0 + gp;
        const int gc1 = gc0 + 8;
#pragma unroll
        for (int q = 0; q < 16; q++) {
            const int k0 = q * 16 + 2 * t4;
            float x, y;
            x = U[(size_t)k0 * 1024 + gc0];       y = U[(size_t)(k0 + 1) * 1024 + gc0];
            split_pack(x, y, Ahi[q][0], Alo[q][0]);
            x = U[(size_t)k0 * 1024 + gc1];       y = U[(size_t)(k0 + 1) * 1024 + gc1];
            split_pack(x, y, Ahi[q][1], Alo[q][1]);
            x = U[(size_t)(k0 + 8) * 1024 + gc0]; y = U[(size_t)(k0 + 9) * 1024 + gc0];
            split_pack(x, y, Ahi[q][2], Alo[q][2]);
            x = U[(size_t)(k0 + 8) * 1024 + gc1]; y = U[(size_t)(k0 + 9) * 1024 + gc1];
            split_pack(x, y, Ahi[q][3], Alo[q][3]);
        }
#pragma unroll
        for (int q2 = 0; q2 < 8; q2++) {
            const int q = 16 + q2;
            const int k0 = q2 * 16 + 2 * t4;
            float x, y;
            x = Wm[(size_t)k0 * 1024 + gc0];       y = Wm[(size_t)(k0 + 1) * 1024 + gc0];
            split_pack(x, y, Ahi[q][0], Alo[q][0]);
            x = Wm[(size_t)k0 * 1024 + gc1];       y = Wm[(size_t)(k0 + 1) * 1024 + gc1];
            split_pack(x, y, Ahi[q][1], Alo[q][1]);
            x = Wm[(size_t)(k0 + 8) * 1024 + gc0]; y = Wm[(size_t)(k0 + 9) * 1024 + gc0];
            split_pack(x, y, Ahi[q][2], Alo[q][2]);
            x = Wm[(size_t)(k0 + 8) * 1024 + gc1]; y = Wm[(size_t)(k0 + 9) * 1024 + gc1];
            split_pack(x, y, Ahi[q][3], Alo[q][3]);
        }
    }

    float ccar = 0.f, hcar = 0.f;
    const float* tsrow = ts + (size_t)(bg0 + ob) * S_;
    float tt = tsrow[0];

    // x prefetch: warp w owns batch bg0+w; thread covers 4 consecutive x dims
    const float* xbase = X + (size_t)(bg0 + w) * S_ * I_ + lane * 4;
    float4 xv = *reinterpret_cast<const float4*>(xbase);   // x(0)

    for (int s = 0; s < S_; s++) {
        const int cur = s & 1, nxt = cur ^ 1;

        // ---- fine-grained: warp w polls producer w's flag, stages h chunk w
        if (s > 0) {
            if (lane == 0) {
                const unsigned tgt = (unsigned)s;
                while (ld_acq(&g_flag[grp][w][0]) < tgt) {}
            }
            __syncwarp();
        }
        {
            const int p = lane & 15;
#pragma unroll
            for (int i = 0; i < 4; i++) {
                const int b = 2 * i + (lane >> 4);
                uint2 u = ldcg_u2(reinterpret_cast<const uint2*>(
                    &g_hpack[cur][(bg0 + b) * H_ + 32 * w + 2 * p]));
                const int dst = b * RPITCH + 16 * w + p;
                Hhi[dst] = __byte_perm(u.x, u.y, 0x5410);
                Hlo[dst] = __byte_perm(u.x, u.y, 0x7632);
            }
        }
        // ---- stage x(s) (prefetched): warp w -> row w, pairs 128..191
        {
            uint32_t h0, l0, h1, l1;
            split_pack(xv.x, xv.y, h0, l0);
            split_pack(xv.z, xv.w, h1, l1);
            const int dst = w * RPITCH + 128 + lane * 2;
            Hhi[dst] = h0; Hhi[dst + 1] = h1;
            Hlo[dst] = l0; Hlo[dst + 1] = l1;
        }
        __syncthreads();

        // ---- MMA: K = 384 (24 q), 3 independent accumulator chains
        float4 Da = make_float4(0.f, 0.f, 0.f, 0.f);
        float4 Db = make_float4(0.f, 0.f, 0.f, 0.f);
        float4 Dc = make_float4(0.f, 0.f, 0.f, 0.f);
#pragma unroll
        for (int q = 0; q < 24; q++) {
            const int base = gp * RPITCH + q * 8 + t4;
            uint32_t bh0 = Hhi[base], bh1 = Hhi[base + 4];
            uint32_t bl0 = Hlo[base], bl1 = Hlo[base + 4];
            mma_bf16(Da, Ahi[q], bh0, bh1);
            mma_bf16(Db, Ahi[q], bl0, bl1);
            mma_bf16(Dc, Alo[q], bh0, bh1);
        }
        float4 D = make_float4(Da.x + Db.x + Dc.x, Da.y + Db.y + Dc.y,
                               Da.z + Db.z + Dc.z, Da.w + Db.w + Dc.w);

        {
            const int r0 = 16 * w + gp;
            d_sm[r0 * 10 + 2 * t4] = D.x;
            d_sm[r0 * 10 + 2 * t4 + 1] = D.y;
            d_sm[(r0 + 8) * 10 + 2 * t4] = D.z;
            d_sm[(r0 + 8) * 10 + 2 * t4 + 1] = D.w;
        }
        __syncthreads();

        float p0 = d_sm[(0 * 32 + oj) * 10 + ob];
        float p1 = d_sm[(1 * 32 + oj) * 10 + ob];
        float p2 = d_sm[(2 * 32 + oj) * 10 + ob];
        float p3 = d_sm[(3 * 32 + oj) * 10 + ob];

        float it = sigf(Bi + p0);
        float ft = sigf(Bf + p1);
        float gt = tanhf(Bg + p2);
        float ot = sigf(Bo + p3);
        float cn = ft * ccar + it * gt;
        float hn = ot * tanhf(cn);

        float ic = fmodf(tt + sv, pv);
        float mask;
        if (ic <= on_mid)      mask = ic / on_mid;
        else if (ic <= on_end) mask = (on_end - ic) / on_mid;
        else                   mask = OFF_SLOPE * (ic / pv);

        ccar = mask * cn + (1.f - mask) * ccar;
        float h2 = mask * hn + (1.f - mask) * hcar;
        hcar = h2;

        // publish packed h
        __nv_bfloat16 hb = __float2bfloat16(h2);
        __nv_bfloat16 lb = __float2bfloat16(h2 - __bfloat162float(hb));
        g_hpack[nxt][(bg0 + ob) * H_ + jg] =
            (uint32_t)__bfloat16_as_ushort(hb) |
            ((uint32_t)__bfloat16_as_ushort(lb) << 16);

        // prefetch x(s+1) + ts(s+1) (recurrence-independent, in flight)
        if (s + 1 < S_) {
            xv = *reinterpret_cast<const float4*>(xbase + (size_t)(s + 1) * I_);
            tt = tsrow[s + 1];
        }

        // all 8 warps' publishes done -> release our flag
        __syncthreads();
        if (tid == 0) st_release(&g_flag[grp][hslc][0], (unsigned)(s + 1));

        // off critical path: output store
        out[((size_t)(bg0 + ob) * S_ + s) * H_ + jg] = h2;
    }

    if (writeTails) {
        const size_t baseT = (size_t)B_ * S_ * H_;
        out[baseT + (size_t)(bg0 + ob) * H_ + jg] = hcar;                    // h_T
        out[baseT + (size_t)B_ * H_ + (size_t)(bg0 + ob) * H_ + jg] = ccar;  // c_T
    }
}

// ---------------- launch ----------------
extern "C" void kernel_launch(void* const* d_in, const int* in_sizes, int n_in,
                              void* d_out, int out_size) {
    const float* x    = (const float*)d_in[0];
    const float* ts   = (const float*)d_in[1];
    const float* W    = (const float*)d_in[2];
    const float* U    = (const float*)d_in[3];
    const float* bias = (const float*)d_in[4];
    const float* Per  = (const float*)d_in[5];
    const float* Shf  = (const float*)d_in[6];
    const float* Oe   = (const float*)d_in[7];
    float* out = (float*)d_out;

    init_k<<<64, 256>>>();

    const long long need = (long long)B_ * S_ * H_ + 2LL * B_ * H_;
    int writeTails = ((long long)out_size >= need) ? 1 : 0;
    plstm_rec<<<128, 256>>>(x, U, W, bias, ts, Per, Shf, Oe, out, writeTails);
}

// round 12
// speedup vs baseline: 2.0755x; 1.0322x over previous
#include <cuda_runtime.h>
#include <cuda_bf16.h>
#include <cstdint>

#define B_   128
#define S_   1024
#define I_   128
#define H_   256
#define OFF_SLOPE 0.001f

// ---------------- device scratch (static, no allocations) ----------------
__device__ __align__(16) unsigned g_hpack[2][B_ * H_];  // packed (bf16 hi | lo<<16)
__device__ __align__(128) unsigned g_flag[16][8][32];   // [grp][cta], own 128B line

__device__ __forceinline__ void split_pack(float x, float y,
                                           uint32_t& hi, uint32_t& lo) {
    __nv_bfloat16 hx = __float2bfloat16(x);
    __nv_bfloat16 hy = __float2bfloat16(y);
    __nv_bfloat16 lx = __float2bfloat16(x - __bfloat162float(hx));
    __nv_bfloat16 ly = __float2bfloat16(y - __bfloat162float(hy));
    hi = (uint32_t)__bfloat16_as_ushort(hx) | ((uint32_t)__bfloat16_as_ushort(hy) << 16);
    lo = (uint32_t)__bfloat16_as_ushort(lx) | ((uint32_t)__bfloat16_as_ushort(ly) << 16);
}

__device__ __forceinline__ void mma_bf16(float4& d, const uint32_t* a,
                                         uint32_t b0, uint32_t b1) {
    asm volatile(
        "mma.sync.aligned.m16n8k16.row.col.f32.bf16.bf16.f32 "
        "{%0,%1,%2,%3}, {%4,%5,%6,%7}, {%8,%9}, {%0,%1,%2,%3};"
        : "+f"(d.x), "+f"(d.y), "+f"(d.z), "+f"(d.w)
        : "r"(a[0]), "r"(a[1]), "r"(a[2]), "r"(a[3]), "r"(b0), "r"(b1));
}

// ---------------- init: zero flags + h0 ----------------
__global__ void init_k() {
    unsigned t = blockIdx.x * blockDim.x + threadIdx.x;
    if (t < 16u * 8u * 32u) ((unsigned*)g_flag)[t] = 0u;
    for (unsigned i = t; i < 2u * B_ * H_; i += gridDim.x * blockDim.x)
        ((unsigned*)g_hpack)[i] = 0u;
}

__device__ __forceinline__ float sigf(float x) { return 1.0f / (1.0f + __expf(-x)); }

__device__ __forceinline__ unsigned ld_acq(const unsigned* p) {
    unsigned v;
    asm volatile("ld.global.acquire.gpu.u32 %0, [%1];" : "=r"(v) : "l"(p) : "memory");
    return v;
}
__device__ __forceinline__ void st_release(unsigned* p, unsigned v) {
    asm volatile("st.release.gpu.global.u32 [%0], %1;" :: "l"(p), "r"(v) : "memory");
}
__device__ __forceinline__ uint2 ldcg_u2(const uint2* p) {
    uint2 v;
    asm volatile("ld.global.cg.v2.u32 {%0,%1}, [%2];"
                 : "=r"(v.x), "=r"(v.y) : "l"(p));
    return v;
}

#define RPITCH 196   // SMEM row pitch (u32 pairs): 128 h + 64 x + pad

// fused persistent PLSTM: 128 CTAs = 16 groups (8 batches) x 8 slices.
// D[128 gates, 8 b] = [U^T|W^T][128,384] @ [h; x_t][384,8], bf16x3 mma.
// SOFTWARE PIPELINE: the x*W part (q 16..23, recurrence-independent) of
// step s+1 is computed right after releasing flag(s), hiding the inter-CTA
// barrier latency; the h*U part (q 0..15) runs after the poll.
__global__ __launch_bounds__(256, 1) void plstm_rec(
    const float* __restrict__ X, const float* __restrict__ U,
    const float* __restrict__ Wm, const float* __restrict__ bias,
    const float* __restrict__ ts, const float* __restrict__ Per,
    const float* __restrict__ Shf, const float* __restrict__ Oe,
    float* __restrict__ out, int writeTails) {
    __shared__ __align__(16) uint32_t Hhi[8 * RPITCH];
    __shared__ __align__(16) uint32_t Hlo[8 * RPITCH];
    __shared__ __align__(16) float d_sm[128 * 10];

    const int tid = threadIdx.x;
    const int lane = tid & 31;
    const int w = tid >> 5;
    const int gp = lane >> 2;
    const int t4 = lane & 3;
    const int grp = blockIdx.x >> 3;
    const int hslc = blockIdx.x & 7;
    const int bg0 = grp * 8;
    const int hs = hslc * 32;
    const int ob = tid >> 5;
    const int oj = lane;
    const int jg = hs + oj;

    const float pv = fabsf(Per[jg]);
    const float sv = Shf[jg];
    const float oe = fabsf(Oe[jg]);
    const float on_end = oe * pv;
    const float on_mid = (oe * 0.5f) * pv;

    const float Bi = bias[jg], Bf = bias[256 + jg];
    const float Bg = bias[512 + jg], Bo = bias[768 + jg];

    // one-time: preload A^T fragments, q 0..15 = U, q 16..23 = W (hi/lo).
    uint32_t Ahi[24][4], Alo[24][4];
    {
        const int gblk = w >> 1;
        const int u0 = (w & 1) * 16;
        const int gc0 = gblk * 256 + hs + u0 + gp;
        const int gc1 = gc0 + 8;
#pragma unroll
        for (int q = 0; q < 16; q++) {
            const int k0 = q * 16 + 2 * t4;
            float x, y;
            x = U[(size_t)k0 * 1024 + gc0];       y = U[(size_t)(k0 + 1) * 1024 + gc0];
            split_pack(x, y, Ahi[q][0], Alo[q][0]);
            x = U[(size_t)k0 * 1024 + gc1];       y = U[(size_t)(k0 + 1) * 1024 + gc1];
            split_pack(x, y, Ahi[q][1], Alo[q][1]);
            x = U[(size_t)(k0 + 8) * 1024 + gc0]; y = U[(size_t)(k0 + 9) * 1024 + gc0];
            split_pack(x, y, Ahi[q][2], Alo[q][2]);
            x = U[(size_t)(k0 + 8) * 1024 + gc1]; y = U[(size_t)(k0 + 9) * 1024 + gc1];
            split_pack(x, y, Ahi[q][3], Alo[q][3]);
        }
#pragma unroll
        for (int q2 = 0; q2 < 8; q2++) {
            const int q = 16 + q2;
            const int k0 = q2 * 16 + 2 * t4;
            float x, y;
            x = Wm[(size_t)k0 * 1024 + gc0];       y = Wm[(size_t)(k0 + 1) * 1024 + gc0];
            split_pack(x, y, Ahi[q][0], Alo[q][0]);
            x = Wm[(size_t)k0 * 1024 + gc1];       y = Wm[(size_t)(k0 + 1) * 1024 + gc1];
            split_pack(x, y, Ahi[q][1], Alo[q][1]);
            x = Wm[(size_t)(k0 + 8) * 1024 + gc0]; y = Wm[(size_t)(k0 + 9) * 1024 + gc0];
            split_pack(x, y, Ahi[q][2], Alo[q][2]);
            x = Wm[(size_t)(k0 + 8) * 1024 + gc1]; y = Wm[(size_t)(k0 + 9) * 1024 + gc1];
            split_pack(x, y, Ahi[q][3], Alo[q][3]);
        }
    }

    float ccar = 0.f, hcar = 0.f;
    const float* tsrow = ts + (size_t)(bg0 + ob) * S_;
    float tt = tsrow[0];

    // x stream: warp w owns batch bg0+w; thread covers 4 consecutive dims
    const float* xbase = X + (size_t)(bg0 + w) * S_ * I_ + lane * 4;
    float4 xv = *reinterpret_cast<const float4*>(xbase);   // x(0)

    // ---- prologue: stage x(0), compute xW(0) into accumulators ----
    float4 Da, Db, Dc;
    {
        uint32_t h0, l0, h1, l1;
        split_pack(xv.x, xv.y, h0, l0);
        split_pack(xv.z, xv.w, h1, l1);
        const int dst = w * RPITCH + 128 + lane * 2;
        Hhi[dst] = h0; Hhi[dst + 1] = h1;
        Hlo[dst] = l0; Hlo[dst + 1] = l1;
    }
    __syncthreads();
    Da = make_float4(0.f, 0.f, 0.f, 0.f);
    Db = make_float4(0.f, 0.f, 0.f, 0.f);
    Dc = make_float4(0.f, 0.f, 0.f, 0.f);
#pragma unroll
    for (int q = 16; q < 24; q++) {
        const int base = gp * RPITCH + q * 8 + t4;
        uint32_t bh0 = Hhi[base], bh1 = Hhi[base + 4];
        uint32_t bl0 = Hlo[base], bl1 = Hlo[base + 4];
        mma_bf16(Da, Ahi[q], bh0, bh1);
        mma_bf16(Db, Ahi[q], bl0, bl1);
        mma_bf16(Dc, Alo[q], bh0, bh1);
    }
    xv = *reinterpret_cast<const float4*>(xbase + I_);      // x(1)

    for (int s = 0; s < S_; s++) {
        const int cur = s & 1, nxt = cur ^ 1;

        // ---- poll producer w's flag for h(s), stage h chunk w ----
        if (s > 0) {
            if (lane == 0) {
                const unsigned tgt = (unsigned)s;
                while (ld_acq(&g_flag[grp][w][0]) < tgt) {}
            }
            __syncwarp();
        }
        {
            const int p = lane & 15;
#pragma unroll
            for (int i = 0; i < 4; i++) {
                const int b = 2 * i + (lane >> 4);
                uint2 u = ldcg_u2(reinterpret_cast<const uint2*>(
                    &g_hpack[cur][(bg0 + b) * H_ + 32 * w + 2 * p]));
                const int dst = b * RPITCH + 16 * w + p;
                Hhi[dst] = __byte_perm(u.x, u.y, 0x5410);
                Hlo[dst] = __byte_perm(u.x, u.y, 0x7632);
            }
        }
        __syncthreads();                         // sync A: h(s) staged

        // ---- h*U MMA (q 0..15), accumulating onto xW(s) ----
#pragma unroll
        for (int q = 0; q < 16; q++) {
            const int base = gp * RPITCH + q * 8 + t4;
            uint32_t bh0 = Hhi[base], bh1 = Hhi[base + 4];
            uint32_t bl0 = Hlo[base], bl1 = Hlo[base + 4];
            mma_bf16(Da, Ahi[q], bh0, bh1);
            mma_bf16(Db, Ahi[q], bl0, bl1);
            mma_bf16(Dc, Alo[q], bh0, bh1);
        }
        float4 D = make_float4(Da.x + Db.x + Dc.x, Da.y + Db.y + Dc.y,
                               Da.z + Db.z + Dc.z, Da.w + Db.w + Dc.w);
        {
            const int r0 = 16 * w + gp;
            d_sm[r0 * 10 + 2 * t4] = D.x;
            d_sm[r0 * 10 + 2 * t4 + 1] = D.y;
            d_sm[(r0 + 8) * 10 + 2 * t4] = D.z;
            d_sm[(r0 + 8) * 10 + 2 * t4 + 1] = D.w;
        }
        __syncthreads();                         // sync B: D scattered

        // ---- cell ----
        float p0 = d_sm[(0 * 32 + oj) * 10 + ob];
        float p1 = d_sm[(1 * 32 + oj) * 10 + ob];
        float p2 = d_sm[(2 * 32 + oj) * 10 + ob];
        float p3 = d_sm[(3 * 32 + oj) * 10 + ob];

        float it = sigf(Bi + p0);
        float ft = sigf(Bf + p1);
        float gt = tanhf(Bg + p2);
        float ot = sigf(Bo + p3);
        float cn = ft * ccar + it * gt;
        float hn = ot * tanhf(cn);

        float ic = fmodf(tt + sv, pv);
        float mask;
        if (ic <= on_mid)      mask = ic / on_mid;
        else if (ic <= on_end) mask = (on_end - ic) / on_mid;
        else                   mask = OFF_SLOPE * (ic / pv);

        ccar = mask * cn + (1.f - mask) * ccar;
        float h2 = mask * hn + (1.f - mask) * hcar;
        hcar = h2;

        // publish packed h(s+1-state)
        __nv_bfloat16 hb = __float2bfloat16(h2);
        __nv_bfloat16 lb = __float2bfloat16(h2 - __bfloat162float(hb));
        g_hpack[nxt][(bg0 + ob) * H_ + jg] =
            (uint32_t)__bfloat16_as_ushort(hb) |
            ((uint32_t)__bfloat16_as_ushort(lb) << 16);

        __syncthreads();                         // sync C: publishes done
        if (tid == 0) st_release(&g_flag[grp][hslc][0], (unsigned)(s + 1));

        // ==== barrier-hiding window: work not needing h(s+1) ====
        out[((size_t)(bg0 + ob) * S_ + s) * H_ + jg] = h2;

        if (s + 1 < S_) {
            // stage x(s+1) (prefetched in xv)
            uint32_t h0, l0, h1, l1;
            split_pack(xv.x, xv.y, h0, l0);
            split_pack(xv.z, xv.w, h1, l1);
            const int dst = w * RPITCH + 128 + lane * 2;
            Hhi[dst] = h0; Hhi[dst + 1] = h1;
            Hlo[dst] = l0; Hlo[dst + 1] = l1;
            __syncthreads();                     // sync D: x(s+1) staged

            // xW(s+1) MMA into fresh accumulators
            Da = make_float4(0.f, 0.f, 0.f, 0.f);
            Db = make_float4(0.f, 0.f, 0.f, 0.f);
            Dc = make_float4(0.f, 0.f, 0.f, 0.f);
#pragma unroll
            for (int q = 16; q < 24; q++) {
                const int base = gp * RPITCH + q * 8 + t4;
                uint32_t bh0 = Hhi[base], bh1 = Hhi[base + 4];
                uint32_t bl0 = Hlo[base], bl1 = Hlo[base + 4];
                mma_bf16(Da, Ahi[q], bh0, bh1);
                mma_bf16(Db, Ahi[q], bl0, bl1);
                mma_bf16(Dc, Alo[q], bh0, bh1);
            }
            // prefetch x(s+2), ts(s+1)
            if (s + 2 < S_)
                xv = *reinterpret_cast<const float4*>(xbase + (size_t)(s + 2) * I_);
            tt = tsrow[s + 1];
        }
    }

    if (writeTails) {
        const size_t baseT = (size_t)B_ * S_ * H_;
        out[baseT + (size_t)(bg0 + ob) * H_ + jg] = hcar;                    // h_T
        out[baseT + (size_t)B_ * H_ + (size_t)(bg0 + ob) * H_ + jg] = ccar;  // c_T
    }
}

// ---------------- launch ----------------
extern "C" void kernel_launch(void* const* d_in, const int* in_sizes, int n_in,
                              void* d_out, int out_size) {
    const float* x    = (const float*)d_in[0];
    const float* ts   = (const float*)d_in[1];
    const float* W    = (const float*)d_in[2];
    const float* U    = (const float*)d_in[3];
    const float* bias = (const float*)d_in[4];
    const float* Per  = (const float*)d_in[5];
    const float* Shf  = (const float*)d_in[6];
    const float* Oe   = (const float*)d_in[7];
    float* out = (float*)d_out;

    init_k<<<64, 256>>>();

    const long long need = (long long)B_ * S_ * H_ + 2LL * B_ * H_;
    int writeTails = ((long long)out_size >= need) ? 1 : 0;
    plstm_rec<<<128, 256>>>(x, U, W, bias, ts, Per, Shf, Oe, out, writeTails);
}